// round 16
// baseline (speedup 1.0000x reference)
#include <cuda_runtime.h>
#include <cuda_fp16.h>
#include <cstdint>

#define N_USERS 100000
#define N_ITEMS 200000
#define N_NODES 300000
#define EMB     64
#define NNZ     9600000
#define ROW_PAD 80                     // Poisson(32): P(deg>80) ~ 1e-11/row -> safe for any seed
#define SPMM_BLOCKS (148 * 8)
#define WARPS_PER_BLOCK 8
#define T 256
#define G_INIT  ((N_NODES * EMB / 4 + T - 1) / T)   // init-work blocks
#define G_EDGE2 ((NNZ / 2 + T - 1) / T)             // scatter-work blocks (2 edges/thread)

// -------- static device scratch (allocation-free) --------
// g_cursor: zero at module load; k_spmm_last re-zeroes every row it consumes,
// so every kernel_launch call starts with an all-zero cursor array.
__device__ __half g_ego[3][(size_t)N_NODES * EMB];        // ego0 / e1 / e2 (fp16)
__device__ int2   g_edgepad[(size_t)N_NODES * ROW_PAD];   // padded CSR (col<<7, half2(val,val))
__device__ int    g_cursor[N_NODES];                      // per-row fill count

// -------- 1) fused build: low blocks init ego0, high blocks scatter edges --------
__global__ void k_build(const float4* __restrict__ user4,
                        const float4* __restrict__ item4,
                        const int2* __restrict__ rows2,
                        const int2* __restrict__ cols2,
                        const float2* __restrict__ vals2) {
    if (blockIdx.x < G_INIT) {
        // ---- init: g_ego[0] = fp16(cat(user,item)) ----
        const int n4  = N_NODES * EMB / 4;
        const int nu4 = N_USERS * EMB / 4;
        int i = blockIdx.x * blockDim.x + threadIdx.x;
        if (i >= n4) return;
        float4 v = (i < nu4) ? __ldcs(&user4[i]) : __ldcs(&item4[i - nu4]);
        half2* h = reinterpret_cast<half2*>(g_ego[0]);
        h[2 * i]     = __floats2half2_rn(v.x, v.y);
        h[2 * i + 1] = __floats2half2_rn(v.z, v.w);
    } else {
        // ---- scatter: COO -> padded CSR, 2 edges per thread ----
        // col stored PRE-SCALED (<<7 = byte offset of its 128B ego row) so the
        // SpMM gather needs no per-edge multiply.
        int i = (blockIdx.x - G_INIT) * blockDim.x + threadIdx.x;
        if (i >= NNZ / 2) return;
        int2   r = __ldcs(&rows2[i]);
        int2   c = __ldcs(&cols2[i]);
        float2 v = __ldcs(&vals2[i]);

        int idx0 = atomicAdd(&g_cursor[r.x], 1);
        if (idx0 < ROW_PAD) {
            half2 hv = __float2half2_rn(v.x);
            int hvbits; memcpy(&hvbits, &hv, 4);
            g_edgepad[(size_t)r.x * ROW_PAD + idx0] = make_int2(c.x << 7, hvbits);
        }
        int idx1 = atomicAdd(&g_cursor[r.y], 1);
        if (idx1 < ROW_PAD) {
            half2 hv = __float2half2_rn(v.y);
            int hvbits; memcpy(&hvbits, &hv, 4);
            g_edgepad[(size_t)r.y * ROW_PAD + idx1] = make_int2(c.y << 7, hvbits);
        }
    }
}

// -------- paired-edge chunk consumer: up to 32 edges, 2 edges/LDG.64 (.cg) --------
// einb = byte pointer to the gather table; e.x is already the row byte-offset;
// sub8 = this lane's byte slice within the row. Address = einb + e.x + sub8 (adds only).
__device__ __forceinline__ void consume_chunk(const char* __restrict__ einb,
                                              const int2* __restrict__ cb,
                                              int m, int hf, int sub8,
                                              float2& acc0, float2& acc1) {
    half2 a0 = __float2half2_rn(0.f), a1 = a0;       // fp16 chunk accumulators (<=16 terms)
    if (m == 32) {
        #pragma unroll
        for (int j = 0; j < 32; j += 2) {
            int2 e = cb[j + hf];                      // broadcast LDS per half-warp
            half2 v2 = *reinterpret_cast<half2*>(&e.y);
            uint2 x = __ldcg(reinterpret_cast<const uint2*>(einb + (unsigned)(e.x + sub8)));
            a0 = __hfma2(v2, *reinterpret_cast<half2*>(&x.x), a0);
            a1 = __hfma2(v2, *reinterpret_cast<half2*>(&x.y), a1);
        }
    } else {
        for (int j = 0; j < m; j += 2) {              // odd tail: zero-padded slot is a no-op
            int2 e = cb[j + hf];
            half2 v2 = *reinterpret_cast<half2*>(&e.y);
            uint2 x = __ldcg(reinterpret_cast<const uint2*>(einb + (unsigned)(e.x + sub8)));
            a0 = __hfma2(v2, *reinterpret_cast<half2*>(&x.x), a0);
            a1 = __hfma2(v2, *reinterpret_cast<half2*>(&x.y), a1);
        }
    }
    float2 f0 = __half22float2(a0);
    float2 f1 = __half22float2(a1);
    acc0.x += f0.x; acc0.y += f0.y;
    acc1.x += f1.x; acc1.y += f1.y;
}

// Pipelined SpMM row loop shared by mid/last (EPILOGUE pasted per kernel).
#define SPMM_PIPELINED_LOOP(EINB, EPILOGUE)                                             \
    int row = warp0;                                                                    \
    int par = 0;                                                                        \
    int cnt_cur = 0;                                                                    \
    if (row < N_NODES) {                                                                \
        cnt_cur = __ldg(&g_cursor[row]);                                                \
        int2 ev = make_int2(0, 0);                                                      \
        if (lane < cnt_cur) ev = __ldcs(&g_edgepad[(size_t)row * ROW_PAD + lane]);      \
        sbuf[wid][0][0][lane] = ev;                                                     \
    }                                                                                   \
    for (; row < N_NODES; row += nwarps) {                                              \
        __syncwarp();                                                                   \
        const int cnt  = cnt_cur;                                                       \
        const int nrow = row + nwarps;                                                  \
        if (nrow < N_NODES) cnt_cur = __ldg(&g_cursor[nrow]);                           \
        float2 acc0 = make_float2(0.f, 0.f), acc1 = make_float2(0.f, 0.f);              \
        consume_chunk(EINB, sbuf[wid][par][0], min(cnt, 32), hf, sub8, acc0, acc1);     \
        if (nrow < N_NODES) {                       /* prefetch next row chunk0 */      \
            int2 ev = make_int2(0, 0);                                                  \
            if (lane < cnt_cur) ev = __ldcs(&g_edgepad[(size_t)nrow * ROW_PAD + lane]); \
            sbuf[wid][par ^ 1][0][lane] = ev;                                           \
        }                                                                               \
        for (int done = 32; done < cnt; done += 32) {   /* overflow chunks (deg>32) */  \
            int rem = cnt - done;                                                       \
            int2 ev = make_int2(0, 0);                                                  \
            if (lane < rem) ev = __ldcs(&g_edgepad[(size_t)row * ROW_PAD + done + lane]);\
            __syncwarp();                                                               \
            sbuf[wid][par][1][lane] = ev;                                               \
            __syncwarp();                                                               \
            consume_chunk(EINB, sbuf[wid][par][1], min(rem, 32), hf, sub8, acc0, acc1); \
        }                                                                               \
        acc0.x += __shfl_xor_sync(0xffffffffu, acc0.x, 16);                             \
        acc0.y += __shfl_xor_sync(0xffffffffu, acc0.y, 16);                             \
        acc1.x += __shfl_xor_sync(0xffffffffu, acc1.x, 16);                             \
        acc1.y += __shfl_xor_sync(0xffffffffu, acc1.y, 16);                             \
        EPILOGUE;                                                                       \
        par ^= 1;                                                                       \
    }

// -------- 2a) mid layer: eout = fp16(A @ ein) --------
__global__ __launch_bounds__(256) void k_spmm_mid(int pin, int pout) {
    __shared__ int2 sbuf[WARPS_PER_BLOCK][2][2][32];
    const char* __restrict__ einb = reinterpret_cast<const char*>(g_ego[pin]);
    half2* __restrict__ eout      = reinterpret_cast<half2*>(g_ego[pout]);

    const int lane   = threadIdx.x & 31;
    const int wid    = threadIdx.x >> 5;
    const int warp0  = (blockIdx.x * blockDim.x + threadIdx.x) >> 5;
    const int nwarps = (gridDim.x * blockDim.x) >> 5;
    const int hf     = lane >> 4;
    const int sub    = lane & 15;
    const int sub8   = sub * 8;

    SPMM_PIPELINED_LOOP(einb,
        if (lane < 16) {
            uint2 o;
            half2 h0 = __floats2half2_rn(acc0.x, acc0.y);
            half2 h1 = __floats2half2_rn(acc1.x, acc1.y);
            memcpy(&o.x, &h0, 4);
            memcpy(&o.y, &h1, 4);
            reinterpret_cast<uint2*>(eout + (size_t)row * 32)[sub] = o;
        }
    )
}

// -------- 2b) last layer, fully fused:
// out[row] = 0.25 * ( emb[row] + e1[row] + e2[row] + (A @ e2)[row] );
// also re-zeroes g_cursor[row] (this kernel is the final reader of each row).
__global__ __launch_bounds__(256) void k_spmm_last(const float4* __restrict__ user4,
                                                   const float4* __restrict__ item4,
                                                   float4* __restrict__ out4) {
    __shared__ int2 sbuf[WARPS_PER_BLOCK][2][2][32];
    const half2* __restrict__ e1 = reinterpret_cast<const half2*>(g_ego[1]);
    const half2* __restrict__ e2 = reinterpret_cast<const half2*>(g_ego[2]);
    const char* __restrict__ einb = reinterpret_cast<const char*>(g_ego[2]);

    const int lane   = threadIdx.x & 31;
    const int wid    = threadIdx.x >> 5;
    const int warp0  = (blockIdx.x * blockDim.x + threadIdx.x) >> 5;
    const int nwarps = (gridDim.x * blockDim.x) >> 5;
    const int hf     = lane >> 4;
    const int sub    = lane & 15;
    const int sub8   = sub * 8;

    SPMM_PIPELINED_LOOP(einb,
        if (lane == 0) g_cursor[row] = 0;             // reset for next launch (after last read)
        if (lane < 16) {
            float4 base = (row < N_USERS)
                        ? __ldcs(user4 + (size_t)row * 16 + sub)
                        : __ldcs(item4 + (size_t)(row - N_USERS) * 16 + sub);
            uint2 h1 = reinterpret_cast<const uint2*>(e1 + (size_t)row * 32)[sub];
            uint2 h2 = reinterpret_cast<const uint2*>(e2 + (size_t)row * 32)[sub];
            float2 f1a = __half22float2(*reinterpret_cast<half2*>(&h1.x));
            float2 f1b = __half22float2(*reinterpret_cast<half2*>(&h1.y));
            float2 f2a = __half22float2(*reinterpret_cast<half2*>(&h2.x));
            float2 f2b = __half22float2(*reinterpret_cast<half2*>(&h2.y));
            float4 r;
            r.x = (base.x + f1a.x + f2a.x + acc0.x) * 0.25f;
            r.y = (base.y + f1a.y + f2a.y + acc0.y) * 0.25f;
            r.z = (base.z + f1b.x + f2b.x + acc1.x) * 0.25f;
            r.w = (base.w + f1b.y + f2b.y + acc1.y) * 0.25f;
            __stcs(out4 + (size_t)row * 16 + sub, r);
        }
    )
}

extern "C" void kernel_launch(void* const* d_in, const int* in_sizes, int n_in,
                              void* d_out, int out_size) {
    const float* user = (const float*)d_in[0];
    const float* item = (const float*)d_in[1];
    const int*   rows = (const int*)d_in[2];
    const int*   cols = (const int*)d_in[3];
    const float* vals = (const float*)d_in[4];
    float* out = (float*)d_out;

    k_build<<<G_INIT + G_EDGE2, T>>>((const float4*)user, (const float4*)item,
                                     (const int2*)rows, (const int2*)cols,
                                     (const float2*)vals);

    k_spmm_mid<<<SPMM_BLOCKS, T>>>(0, 1);             // layer 1: ego0 -> e1
    k_spmm_mid<<<SPMM_BLOCKS, T>>>(1, 2);             // layer 2: e1   -> e2
    k_spmm_last<<<SPMM_BLOCKS, T>>>((const float4*)user, (const float4*)item,
                                    (float4*)out);    // layer 3 + fused mean + cursor reset
}

// round 17
// speedup vs baseline: 1.0482x; 1.0482x over previous
#include <cuda_runtime.h>
#include <cuda_fp16.h>
#include <cstdint>

#define N_USERS 100000
#define N_ITEMS 200000
#define N_NODES 300000
#define EMB     64
#define NNZ     9600000
#define ROW_PAD 80                     // Poisson(32): P(deg>80) ~ 1e-11/row -> safe for any seed
#define SPMM_BLOCKS (148 * 8)
#define WARPS_PER_BLOCK 8
#define T 256
#define G_INIT  ((N_NODES * EMB / 4 + T - 1) / T)   // init-work blocks
#define G_EDGE2 ((NNZ / 2 + T - 1) / T)             // scatter-work blocks (2 edges/thread)

// -------- static device scratch (allocation-free) --------
// g_cursor: zero at module load; k_spmm_last re-zeroes every row it consumes,
// so every kernel_launch call starts with an all-zero cursor array.
__device__ __half g_ego[3][(size_t)N_NODES * EMB];        // ego0 / e1 / e2 (fp16)
__device__ int2   g_edgepad[(size_t)N_NODES * ROW_PAD];   // padded CSR (col, half2(val,val))
__device__ int    g_cursor[N_NODES];                      // per-row fill count

// -------- 1) fused build: low blocks init ego0, high blocks scatter edges --------
__global__ void k_build(const float4* __restrict__ user4,
                        const float4* __restrict__ item4,
                        const int2* __restrict__ rows2,
                        const int2* __restrict__ cols2,
                        const float2* __restrict__ vals2) {
    if (blockIdx.x < G_INIT) {
        // ---- init: g_ego[0] = fp16(cat(user,item)) ----
        const int n4  = N_NODES * EMB / 4;
        const int nu4 = N_USERS * EMB / 4;
        int i = blockIdx.x * blockDim.x + threadIdx.x;
        if (i >= n4) return;
        float4 v = (i < nu4) ? __ldcs(&user4[i]) : __ldcs(&item4[i - nu4]);
        half2* h = reinterpret_cast<half2*>(g_ego[0]);
        h[2 * i]     = __floats2half2_rn(v.x, v.y);
        h[2 * i + 1] = __floats2half2_rn(v.z, v.w);
    } else {
        // ---- scatter: COO -> padded CSR, 2 edges per thread ----
        // plain stores (no .cs): edgepad stays L2-resident for layer-1 meta reads
        int i = (blockIdx.x - G_INIT) * blockDim.x + threadIdx.x;
        if (i >= NNZ / 2) return;
        int2   r = __ldcs(&rows2[i]);
        int2   c = __ldcs(&cols2[i]);
        float2 v = __ldcs(&vals2[i]);

        int idx0 = atomicAdd(&g_cursor[r.x], 1);
        if (idx0 < ROW_PAD) {
            half2 hv = __float2half2_rn(v.x);
            int hvbits; memcpy(&hvbits, &hv, 4);
            g_edgepad[(size_t)r.x * ROW_PAD + idx0] = make_int2(c.x, hvbits);
        }
        int idx1 = atomicAdd(&g_cursor[r.y], 1);
        if (idx1 < ROW_PAD) {
            half2 hv = __float2half2_rn(v.y);
            int hvbits; memcpy(&hvbits, &hv, 4);
            g_edgepad[(size_t)r.y * ROW_PAD + idx1] = make_int2(c.y, hvbits);
        }
    }
}

// -------- paired-edge chunk consumer: up to 32 edges, 2 edges/LDG.64 (.cg) --------
__device__ __forceinline__ void consume_chunk(const half2* __restrict__ ein,
                                              const int2* __restrict__ cb,
                                              int m, int hf, int sub,
                                              float2& acc0, float2& acc1) {
    half2 a0 = __float2half2_rn(0.f), a1 = a0;       // fp16 chunk accumulators (<=16 terms)
    if (m == 32) {
        #pragma unroll
        for (int j = 0; j < 32; j += 2) {
            int2 e = cb[j + hf];                      // broadcast LDS per half-warp
            half2 v2 = *reinterpret_cast<half2*>(&e.y);
            uint2 x = __ldcg(reinterpret_cast<const uint2*>(ein + (size_t)e.x * 32) + sub);
            a0 = __hfma2(v2, *reinterpret_cast<half2*>(&x.x), a0);
            a1 = __hfma2(v2, *reinterpret_cast<half2*>(&x.y), a1);
        }
    } else {
        for (int j = 0; j < m; j += 2) {              // odd tail: zero-padded slot is a no-op
            int2 e = cb[j + hf];
            half2 v2 = *reinterpret_cast<half2*>(&e.y);
            uint2 x = __ldcg(reinterpret_cast<const uint2*>(ein + (size_t)e.x * 32) + sub);
            a0 = __hfma2(v2, *reinterpret_cast<half2*>(&x.x), a0);
            a1 = __hfma2(v2, *reinterpret_cast<half2*>(&x.y), a1);
        }
    }
    float2 f0 = __half22float2(a0);
    float2 f1 = __half22float2(a1);
    acc0.x += f0.x; acc0.y += f0.y;
    acc1.x += f1.x; acc1.y += f1.y;
}

// Pipelined SpMM row loop shared by mid/last (EPILOGUE pasted per kernel).
#define SPMM_PIPELINED_LOOP(EIN, EPILOGUE)                                              \
    int row = warp0;                                                                    \
    int par = 0;                                                                        \
    int cnt_cur = 0;                                                                    \
    if (row < N_NODES) {                                                                \
        cnt_cur = __ldg(&g_cursor[row]);                                                \
        int2 ev = make_int2(0, 0);                                                      \
        if (lane < cnt_cur) ev = __ldcs(&g_edgepad[(size_t)row * ROW_PAD + lane]);      \
        sbuf[wid][0][0][lane] = ev;                                                     \
    }                                                                                   \
    for (; row < N_NODES; row += nwarps) {                                              \
        __syncwarp();                                                                   \
        const int cnt  = cnt_cur;                                                       \
        const int nrow = row + nwarps;                                                  \
        if (nrow < N_NODES) cnt_cur = __ldg(&g_cursor[nrow]);                           \
        float2 acc0 = make_float2(0.f, 0.f), acc1 = make_float2(0.f, 0.f);              \
        consume_chunk(EIN, sbuf[wid][par][0], min(cnt, 32), hf, sub, acc0, acc1);       \
        if (nrow < N_NODES) {                       /* prefetch next row chunk0 */      \
            int2 ev = make_int2(0, 0);                                                  \
            if (lane < cnt_cur) ev = __ldcs(&g_edgepad[(size_t)nrow * ROW_PAD + lane]); \
            sbuf[wid][par ^ 1][0][lane] = ev;                                           \
        }                                                                               \
        for (int done = 32; done < cnt; done += 32) {   /* overflow chunks (deg>32) */  \
            int rem = cnt - done;                                                       \
            int2 ev = make_int2(0, 0);                                                  \
            if (lane < rem) ev = __ldcs(&g_edgepad[(size_t)row * ROW_PAD + done + lane]);\
            __syncwarp();                                                               \
            sbuf[wid][par][1][lane] = ev;                                               \
            __syncwarp();                                                               \
            consume_chunk(EIN, sbuf[wid][par][1], min(rem, 32), hf, sub, acc0, acc1);   \
        }                                                                               \
        acc0.x += __shfl_xor_sync(0xffffffffu, acc0.x, 16);                             \
        acc0.y += __shfl_xor_sync(0xffffffffu, acc0.y, 16);                             \
        acc1.x += __shfl_xor_sync(0xffffffffu, acc1.x, 16);                             \
        acc1.y += __shfl_xor_sync(0xffffffffu, acc1.y, 16);                             \
        EPILOGUE;                                                                       \
        par ^= 1;                                                                       \
    }

// -------- 2a) mid layer: eout = fp16(A @ ein) --------
__global__ __launch_bounds__(256) void k_spmm_mid(int pin, int pout) {
    __shared__ int2 sbuf[WARPS_PER_BLOCK][2][2][32];
    const half2* __restrict__ ein = reinterpret_cast<const half2*>(g_ego[pin]);
    half2* __restrict__ eout      = reinterpret_cast<half2*>(g_ego[pout]);

    const int lane   = threadIdx.x & 31;
    const int wid    = threadIdx.x >> 5;
    const int warp0  = (blockIdx.x * blockDim.x + threadIdx.x) >> 5;
    const int nwarps = (gridDim.x * blockDim.x) >> 5;
    const int hf     = lane >> 4;
    const int sub    = lane & 15;

    SPMM_PIPELINED_LOOP(ein,
        if (lane < 16) {
            uint2 o;
            half2 h0 = __floats2half2_rn(acc0.x, acc0.y);
            half2 h1 = __floats2half2_rn(acc1.x, acc1.y);
            memcpy(&o.x, &h0, 4);
            memcpy(&o.y, &h1, 4);
            reinterpret_cast<uint2*>(eout + (size_t)row * 32)[sub] = o;
        }
    )
}

// -------- 2b) last layer, fully fused:
// out[row] = 0.25 * ( emb[row] + e1[row] + e2[row] + (A @ e2)[row] );
// also re-zeroes g_cursor[row] (this kernel is the final reader of each row).
__global__ __launch_bounds__(256) void k_spmm_last(const float4* __restrict__ user4,
                                                   const float4* __restrict__ item4,
                                                   float4* __restrict__ out4) {
    __shared__ int2 sbuf[WARPS_PER_BLOCK][2][2][32];
    const half2* __restrict__ e1 = reinterpret_cast<const half2*>(g_ego[1]);
    const half2* __restrict__ e2 = reinterpret_cast<const half2*>(g_ego[2]);

    const int lane   = threadIdx.x & 31;
    const int wid    = threadIdx.x >> 5;
    const int warp0  = (blockIdx.x * blockDim.x + threadIdx.x) >> 5;
    const int nwarps = (gridDim.x * blockDim.x) >> 5;
    const int hf     = lane >> 4;
    const int sub    = lane & 15;

    SPMM_PIPELINED_LOOP(e2,
        if (lane == 0) g_cursor[row] = 0;             // reset for next launch (after last read)
        if (lane < 16) {
            float4 base = (row < N_USERS)
                        ? __ldcs(user4 + (size_t)row * 16 + sub)
                        : __ldcs(item4 + (size_t)(row - N_USERS) * 16 + sub);
            uint2 h1 = reinterpret_cast<const uint2*>(e1 + (size_t)row * 32)[sub];
            uint2 h2 = reinterpret_cast<const uint2*>(e2 + (size_t)row * 32)[sub];
            float2 f1a = __half22float2(*reinterpret_cast<half2*>(&h1.x));
            float2 f1b = __half22float2(*reinterpret_cast<half2*>(&h1.y));
            float2 f2a = __half22float2(*reinterpret_cast<half2*>(&h2.x));
            float2 f2b = __half22float2(*reinterpret_cast<half2*>(&h2.y));
            float4 r;
            r.x = (base.x + f1a.x + f2a.x + acc0.x) * 0.25f;
            r.y = (base.y + f1a.y + f2a.y + acc0.y) * 0.25f;
            r.z = (base.z + f1b.x + f2b.x + acc1.x) * 0.25f;
            r.w = (base.w + f1b.y + f2b.y + acc1.y) * 0.25f;
            __stcs(out4 + (size_t)row * 16 + sub, r);
        }
    )
}

extern "C" void kernel_launch(void* const* d_in, const int* in_sizes, int n_in,
                              void* d_out, int out_size) {
    const float* user = (const float*)d_in[0];
    const float* item = (const float*)d_in[1];
    const int*   rows = (const int*)d_in[2];
    const int*   cols = (const int*)d_in[3];
    const float* vals = (const float*)d_in[4];
    float* out = (float*)d_out;

    k_build<<<G_INIT + G_EDGE2, T>>>((const float4*)user, (const float4*)item,
                                     (const int2*)rows, (const int2*)cols,
                                     (const float2*)vals);

    k_spmm_mid<<<SPMM_BLOCKS, T>>>(0, 1);             // layer 1: ego0 -> e1
    k_spmm_mid<<<SPMM_BLOCKS, T>>>(1, 2);             // layer 2: e1   -> e2
    k_spmm_last<<<SPMM_BLOCKS, T>>>((const float4*)user, (const float4*)item,
                                    (float4*)out);    // layer 3 + fused mean + cursor reset
}